// round 13
// baseline (speedup 1.0000x reference)
#include <cuda_runtime.h>
#include <cstdint>

// Problem shape (fixed by the dataset): N=8, T=256, U=128, C=512.
#define N_DIM  8
#define T_DIM  256
#define U_DIM  128
#define U1_DIM 129
#define C_DIM  512
#define ROWS   (N_DIM * T_DIM * U1_DIM)   // 264192

// Diagonal-major scratch, PROBABILITY domain (exp of log-probs), PITCH=128:
//   em of cell (t,u), u<128:  g_emd[d][u]          (cols 0..127, exact fit)
//   bl of cell (t,u), u>=1:   g_bld[d][u-1]        (cols 1..128 -> slots 0..127)
//   bl of cell (t,0):         g_b0 [n][d]          (one scalar per diagonal)
// Rows are 512B, contiguous in d -> one 4KB cp.async.bulk covers a chunk.
// Pads/unwritten slots stay 0.0 (zero-init) == exp(-inf): dead paths add 0.
#define PITCH   128
#define DIAGS   (T_DIM + U_DIM)           // 384
#define DIAG_SZ (DIAGS * PITCH)           // 49152 per sample

#define CH      8                         // diagonals per pipeline chunk
#define NCHUNK  48                        // 384 diagonals (d = 1..384)
#define SLOTS   32                        // smem ring rows = 4 chunks in flight
#define AHEAD   3                         // chunks issued ahead of consumption
#define CHUNK_BYTES (CH * PITCH * 4)      // 4096 per array

static __device__ __align__(16) float g_bld[N_DIM * DIAG_SZ + 512];  // blank (exp)
static __device__ __align__(16) float g_emd[N_DIM * DIAG_SZ + 512];  // emit  (exp)
static __device__ __align__(16) float g_b0 [N_DIM * DIAGS + 128];    // blank col 0
static __device__ float    g_loss[N_DIM];
static __device__ unsigned g_ticket;       // zero-init; last CTA resets to 0

__device__ __forceinline__ void cp16(unsigned int sdst, const void* gsrc) {
    asm volatile("cp.async.cg.shared.global [%0], [%1], 16;\n"
                 :: "r"(sdst), "l"(gsrc));
}
__device__ __forceinline__ void cp_commit() {
    asm volatile("cp.async.commit_group;\n" ::: "memory");
}
__device__ __forceinline__ void cp_wait_all() {
    asm volatile("cp.async.wait_group 0;\n" ::: "memory");
}
__device__ __forceinline__ void bulk_g2s(unsigned int sdst, const void* gsrc,
                                         unsigned int bytes, unsigned int mbar) {
    asm volatile(
        "cp.async.bulk.shared::cta.global.mbarrier::complete_tx::bytes "
        "[%0], [%1], %2, [%3];\n"
        :: "r"(sdst), "l"(gsrc), "r"(bytes), "r"(mbar) : "memory");
}
__device__ __forceinline__ void mbar_init(unsigned int mbar, unsigned int cnt) {
    asm volatile("mbarrier.init.shared.b64 [%0], %1;\n" :: "r"(mbar), "r"(cnt)
                 : "memory");
}
__device__ __forceinline__ void mbar_expect_tx(unsigned int mbar, unsigned int tx) {
    asm volatile("mbarrier.arrive.expect_tx.shared.b64 _, [%0], %1;\n"
                 :: "r"(mbar), "r"(tx) : "memory");
}
__device__ __forceinline__ void mbar_wait(unsigned int mbar, unsigned int phase) {
    asm volatile(
        "{\n\t.reg .pred P;\n"
        "WAIT_%=:\n\t"
        "mbarrier.try_wait.parity.acquire.cta.shared::cta.b64 P, [%0], %1, 0x989680;\n\t"
        "@P bra.uni DONE_%=;\n\t"
        "bra.uni WAIT_%=;\n"
        "DONE_%=:\n\t}"
        :: "r"(mbar), "r"(phase) : "memory");
}
__device__ __forceinline__ void fence_proxy_async_cta() {
    asm volatile("fence.proxy.async.shared::cta;\n" ::: "memory");
}

// ---------------------------------------------------------------------------
// Kernel 1: per-row logsumexp over C=512; write exp(blank-lse), exp(emit-lse)
// into the packed diagonal-major scratch. One warp per row, 4x float4/lane.
// HBM-bound (541 MB stream, measured at the DRAM ceiling ~84%).
// ---------------------------------------------------------------------------
__global__ void __launch_bounds__(256) lse_kernel(const float* __restrict__ act,
                                                  const int*   __restrict__ tgt) {
    int gw   = (blockIdx.x * 256 + threadIdx.x) >> 5;   // global warp = row id
    int lane = threadIdx.x & 31;
    if (gw >= ROWS) return;

    const float4* p4 = reinterpret_cast<const float4*>(act) + (size_t)gw * (C_DIM / 4);
    float4 a = p4[lane];
    float4 b = p4[lane + 32];
    float4 c = p4[lane + 64];
    float4 d = p4[lane + 96];

    float m = fmaxf(fmaxf(fmaxf(a.x, a.y), fmaxf(a.z, a.w)),
                    fmaxf(fmaxf(b.x, b.y), fmaxf(b.z, b.w)));
    m = fmaxf(m, fmaxf(fmaxf(fmaxf(c.x, c.y), fmaxf(c.z, c.w)),
                       fmaxf(fmaxf(d.x, d.y), fmaxf(d.z, d.w))));
#pragma unroll
    for (int o = 16; o; o >>= 1)
        m = fmaxf(m, __shfl_xor_sync(0xffffffffu, m, o));

    float s = __expf(a.x - m) + __expf(a.y - m) + __expf(a.z - m) + __expf(a.w - m);
    s += __expf(b.x - m) + __expf(b.y - m) + __expf(b.z - m) + __expf(b.w - m);
    s += __expf(c.x - m) + __expf(c.y - m) + __expf(c.z - m) + __expf(c.w - m);
    s += __expf(d.x - m) + __expf(d.y - m) + __expf(d.z - m) + __expf(d.w - m);
#pragma unroll
    for (int o = 16; o; o >>= 1)
        s += __shfl_xor_sync(0xffffffffu, s, o);

    if (lane == 0) {
        float lse = m + __logf(s);
        int n   = gw / (T_DIM * U1_DIM);
        int rem = gw % (T_DIM * U1_DIM);
        int t   = rem / U1_DIM;
        int u   = rem % U1_DIM;
        int dg  = t + u;
        float bexp = __expf(a.x - lse);       // lane 0's a.x == act[row, BLANK=0]
        size_t rb = (size_t)n * DIAG_SZ + (size_t)dg * PITCH;
        if (u == 0) g_b0[n * DIAGS + dg] = bexp;
        else        g_bld[rb + u - 1]    = bexp;
        if (u < U_DIM) {
            int tv = __ldg(tgt + n * U_DIM + u);
            g_emd[rb + u] = __expf(__ldg(act + (size_t)gw * C_DIM + tv) - lse);
        }
    }
}

// ---------------------------------------------------------------------------
// Kernel 2: alpha wavefront, ONE WARP per sample, PROBABILITY domain.
//   alpha(t,u) = alpha(t-1,u)*bexp(t-1,u) + alpha(t,u-1)*eexp(t,u-1)
// Lane L owns u = 4L+1..4L+4 (a[0..3]); u=0 is the multiply-only chain a0.
// 2 FMA-pipe ops per cell, zero MUFU. Exact power-of-two renorm every 8
// diagonals (REDUX.MAX on bit patterns; scale = 2^-e; E += e).
// Final: loss = -(logf(v) + E*ln2 + logf(fin)).
// Operand streaming: cp.async.bulk (one 4KB copy per array per chunk, lane 0
// only -- replaces 128 cycles of per-chunk LDGSTS issue) into a 4-slot smem
// ring gated by 4 mbarriers (slot = c&3, parity = (c>>2)&1). After the
// acquire-wait, the whole chunk is prefetched to registers (LDS latency off
// the per-diagonal chain). Folds the final mean via ticket atomic.
// ---------------------------------------------------------------------------
__global__ void __launch_bounds__(32, 1) alpha_kernel(const int* __restrict__ tlen,
                                                      const int* __restrict__ ulen,
                                                      float* __restrict__ out) {
    __shared__ __align__(16) float s_bl[SLOTS][PITCH];
    __shared__ __align__(16) float s_em[SLOTS][PITCH];
    __shared__ __align__(16) float s_b0[DIAGS];
    __shared__ __align__(8)  unsigned long long s_mbar[4];

    int n = blockIdx.x;
    int L = threadIdx.x;
    const float* bld = g_bld + (size_t)n * DIAG_SZ;
    const float* emd = g_emd + (size_t)n * DIAG_SZ;
    const float* b0g = g_b0  + n * DIAGS;

    int Tn = __ldg(tlen + n);
    int Un = __ldg(ulen + n);
    int dLoss = Tn - 1 + Un;

    unsigned int sbl = (unsigned int)__cvta_generic_to_shared(&s_bl[0][0]);
    unsigned int sem = (unsigned int)__cvta_generic_to_shared(&s_em[0][0]);
    unsigned int sb0 = (unsigned int)__cvta_generic_to_shared(&s_b0[0]);
    unsigned int smb = (unsigned int)__cvta_generic_to_shared(&s_mbar[0]);

    if (L == 0) {
#pragma unroll
        for (int i = 0; i < 4; ++i) mbar_init(smb + 8u * i, 1);
    }
    fence_proxy_async_cta();
    __syncwarp();

    // Issue one chunk (8 contiguous rows = 4KB per array) -- lane 0 only.
    auto issue_chunk = [&](int c) {
        if (L == 0) {
            unsigned int mb = smb + 8u * (c & 3);
            unsigned int so = (unsigned int)(c & 3) * CHUNK_BYTES;
            mbar_expect_tx(mb, 2 * CHUNK_BYTES);
            bulk_g2s(sbl + so, bld + (size_t)c * CH * PITCH, CHUNK_BYTES, mb);
            bulk_g2s(sem + so, emd + (size_t)c * CH * PITCH, CHUNK_BYTES, mb);
        }
    };

    // Prologue: b0 table via cp.async (384 floats = 3 warp-instrs), then
    // the first AHEAD chunks via bulk copies.
    cp16(sb0 + 16u * L,        b0g + 4 * L);
    cp16(sb0 + 16u * (L + 32), b0g + 4 * (L + 32));
    cp16(sb0 + 16u * (L + 64), b0g + 4 * (L + 64));
    cp_commit();
#pragma unroll
    for (int c = 0; c < AHEAD; ++c) issue_chunk(c);
    cp_wait_all();                            // b0 resident
    __syncwarp();

    float a0 = 1.0f;                          // alpha[0][0] = exp(0)
    float a[4] = {0.0f, 0.0f, 0.0f, 0.0f};    // 0 == prob of invalid cell
    int   E = 0;                              // accumulated power-of-two scale

    if (dLoss == 0 && L == 0)                 // degenerate Tn=1, Un=0
        g_loss[n] = -__logf(__ldg(b0g));

    int d = 1;
    for (int c = 0; c < NCHUNK; ++c) {
        if (c + AHEAD < NCHUNK) issue_chunk(c + AHEAD);
        mbar_wait(smb + 8u * (c & 3), (unsigned)((c >> 2) & 1));

        // Prefetch the whole chunk to registers: LDS latency overlapped here,
        // off the per-diagonal dependency chain.
        int base = (c & 3) * CH;               // first ring row of this chunk
        float4 blr[CH], emr[CH];
        float  b0r[CH];
#pragma unroll
        for (int k = 0; k < CH; ++k) {
            blr[k] = *reinterpret_cast<const float4*>(&s_bl[base + k][4 * L]);
            emr[k] = *reinterpret_cast<const float4*>(&s_em[base + k][4 * L]);
        }
        {
            float4 q0 = *reinterpret_cast<const float4*>(&s_b0[CH * c]);
            float4 q1 = *reinterpret_cast<const float4*>(&s_b0[CH * c + 4]);
            b0r[0] = q0.x; b0r[1] = q0.y; b0r[2] = q0.z; b0r[3] = q0.w;
            b0r[4] = q1.x; b0r[5] = q1.y; b0r[6] = q1.z; b0r[7] = q1.w;
        }

#pragma unroll
        for (int k = 0; k < CH; ++k, ++d) {
            float4 blv = blr[k];
            float4 emv = emr[k];

            float nb = __shfl_up_sync(0xffffffffu, a[3], 1);  // aprev[4L]
            nb = (L == 0) ? a0 : nb;

            float t0 = fmaf(nb,   emv.x, a[0] * blv.x);
            float t1 = fmaf(a[0], emv.y, a[1] * blv.y);
            float t2 = fmaf(a[1], emv.z, a[2] * blv.z);
            float t3 = fmaf(a[2], emv.w, a[3] * blv.w);
            a0 *= b0r[k];                      // u=0 blank-only chain
            a[0] = t0; a[1] = t1; a[2] = t2; a[3] = t3;

            if (d == dLoss) {                  // warp-uniform, true exactly once
                float fin = (Un == 0) ? __ldg(b0g + dLoss)
                          : __ldg(bld + (size_t)dLoss * PITCH + Un - 1);
                float lv;
                if (Un == 0) {
                    lv = a0;
                } else {
                    int tl = (Un - 1) >> 2, jj = (Un - 1) & 3;
                    float v = (jj == 0) ? t0 : (jj == 1) ? t1
                            : (jj == 2) ? t2 : t3;
                    lv = __shfl_sync(0xffffffffu, v, tl);
                }
                if (L == 0)
                    g_loss[n] = -(__logf(lv) + (float)E * 0.69314718055994531f
                                  + __logf(fin));
            }
        }

        // Renormalize by exact power of two (every 8 diagonals).
        float m = fmaxf(fmaxf(a[0], a[1]), fmaxf(a[2], a[3]));
        m = fmaxf(m, a0);
        unsigned mb = __reduce_max_sync(0xffffffffu, __float_as_uint(m));
        int e = (int)(mb >> 23) - 127;                        // biased exponent
        float sc = __int_as_float((unsigned)(127 - e) << 23); // 2^-e, exact
        a[0] *= sc; a[1] *= sc; a[2] *= sc; a[3] *= sc; a0 *= sc;
        E += e;
    }

    // Fold the mean: last CTA to arrive sums all losses in fixed order.
    __syncwarp();
    __threadfence();
    if (L == 0) {
        unsigned t = atomicAdd(&g_ticket, 1u);
        if (t == N_DIM - 1) {
            __threadfence();
            float s = 0.0f;
#pragma unroll
            for (int i = 0; i < N_DIM; ++i) s += g_loss[i];
            out[0] = s / (float)N_DIM;
            g_ticket = 0;                      // reset for next graph replay
        }
    }
}

extern "C" void kernel_launch(void* const* d_in, const int* in_sizes, int n_in,
                              void* d_out, int out_size) {
    const float* act  = (const float*)d_in[0];
    const int*   tgt  = (const int*)  d_in[1];
    const int*   tlen = (const int*)  d_in[2];
    const int*   ulen = (const int*)  d_in[3];
    float*       out  = (float*)      d_out;

    int blocks = (ROWS + 7) / 8;              // one warp per row, 8 warps/block
    lse_kernel<<<blocks, 256>>>(act, tgt);
    alpha_kernel<<<N_DIM, 32>>>(tlen, ulen, out);
}

// round 14
// speedup vs baseline: 1.1051x; 1.1051x over previous
#include <cuda_runtime.h>
#include <cstdint>

// Problem shape (fixed by the dataset): N=8, T=256, U=128, C=512.
#define N_DIM  8
#define T_DIM  256
#define U_DIM  128
#define U1_DIM 129
#define C_DIM  512
#define ROWS   (N_DIM * T_DIM * U1_DIM)   // 264192

// Diagonal-major scratch, PROBABILITY domain (exp of log-probs), PITCH=128:
//   em of cell (t,u), u<128:  g_emd[d][u]          (cols 0..127, exact fit)
//   bl of cell (t,u), u>=1:   g_bld[d][u-1]        (cols 1..128 -> slots 0..127)
//   bl of cell (t,0):         g_b0 [n][d]          (one scalar per diagonal)
// Rows are 512B. Pads/unwritten slots stay 0.0 (zero-init) == exp(-inf):
// dead paths contribute 0.
#define PITCH   128
#define DIAGS   (T_DIM + U_DIM)           // 384
#define DIAG_SZ (DIAGS * PITCH)           // 49152 per sample

#define CH      8                         // diagonals per pipeline chunk
#define NCHUNK  48                        // 384 diagonals (d = 1..384)
#define SLOTS   64                        // smem ring rows = 8 chunks in flight
#define AHEAD   7                         // chunks issued ahead of consumption

static __device__ __align__(16) float g_bld[N_DIM * DIAG_SZ + 512];  // blank (exp)
static __device__ __align__(16) float g_emd[N_DIM * DIAG_SZ + 512];  // emit  (exp)
static __device__ __align__(16) float g_b0 [N_DIM * DIAGS + 128];    // blank col 0
static __device__ float    g_loss[N_DIM];
static __device__ unsigned g_ticket;       // zero-init; last CTA resets to 0

__device__ __forceinline__ void cp16(unsigned int sdst, const void* gsrc) {
    asm volatile("cp.async.cg.shared.global [%0], [%1], 16;\n"
                 :: "r"(sdst), "l"(gsrc));
}
__device__ __forceinline__ void cp_commit() {
    asm volatile("cp.async.commit_group;\n" ::: "memory");
}
__device__ __forceinline__ void cp_wait7() {
    asm volatile("cp.async.wait_group 7;\n" ::: "memory");
}

// ---------------------------------------------------------------------------
// Kernel 1: per-row logsumexp over C=512; write exp(blank-lse), exp(emit-lse)
// into the packed diagonal-major scratch. One warp per row, 4x float4/lane.
// HBM-bound (541 MB stream, measured at the DRAM ceiling ~84%).
// ---------------------------------------------------------------------------
__global__ void __launch_bounds__(256) lse_kernel(const float* __restrict__ act,
                                                  const int*   __restrict__ tgt) {
    int gw   = (blockIdx.x * 256 + threadIdx.x) >> 5;   // global warp = row id
    int lane = threadIdx.x & 31;
    if (gw >= ROWS) return;

    const float4* p4 = reinterpret_cast<const float4*>(act) + (size_t)gw * (C_DIM / 4);
    float4 a = p4[lane];
    float4 b = p4[lane + 32];
    float4 c = p4[lane + 64];
    float4 d = p4[lane + 96];

    float m = fmaxf(fmaxf(fmaxf(a.x, a.y), fmaxf(a.z, a.w)),
                    fmaxf(fmaxf(b.x, b.y), fmaxf(b.z, b.w)));
    m = fmaxf(m, fmaxf(fmaxf(fmaxf(c.x, c.y), fmaxf(c.z, c.w)),
                       fmaxf(fmaxf(d.x, d.y), fmaxf(d.z, d.w))));
#pragma unroll
    for (int o = 16; o; o >>= 1)
        m = fmaxf(m, __shfl_xor_sync(0xffffffffu, m, o));

    float s = __expf(a.x - m) + __expf(a.y - m) + __expf(a.z - m) + __expf(a.w - m);
    s += __expf(b.x - m) + __expf(b.y - m) + __expf(b.z - m) + __expf(b.w - m);
    s += __expf(c.x - m) + __expf(c.y - m) + __expf(c.z - m) + __expf(c.w - m);
    s += __expf(d.x - m) + __expf(d.y - m) + __expf(d.z - m) + __expf(d.w - m);
#pragma unroll
    for (int o = 16; o; o >>= 1)
        s += __shfl_xor_sync(0xffffffffu, s, o);

    if (lane == 0) {
        float lse = m + __logf(s);
        int n   = gw / (T_DIM * U1_DIM);
        int rem = gw % (T_DIM * U1_DIM);
        int t   = rem / U1_DIM;
        int u   = rem % U1_DIM;
        int dg  = t + u;
        float bexp = __expf(a.x - lse);       // lane 0's a.x == act[row, BLANK=0]
        size_t rb = (size_t)n * DIAG_SZ + (size_t)dg * PITCH;
        if (u == 0) g_b0[n * DIAGS + dg] = bexp;
        else        g_bld[rb + u - 1]    = bexp;
        if (u < U_DIM) {
            int tv = __ldg(tgt + n * U_DIM + u);
            g_emd[rb + u] = __expf(__ldg(act + (size_t)gw * C_DIM + tv) - lse);
        }
    }
}

// ---------------------------------------------------------------------------
// Kernel 2: alpha wavefront, ONE WARP per sample, PROBABILITY domain.
//   alpha(t,u) = alpha(t-1,u)*bexp(t-1,u) + alpha(t,u-1)*eexp(t,u-1)
// Lane L owns u = 4L+1..4L+4 (a[0..3]); u=0 is the multiply-only chain a0.
// 2 FMA-pipe ops per cell, zero MUFU. Exact power-of-two renorm every 8
// diagonals (REDUX.MAX on bit patterns; scale = 2^-e; E += e).
// Final: loss = -(logf(v) + E*ln2 + logf(fin)).
// Operands stream via a 64-row cp.async ring: 8 chunks = 64 diagonals in
// flight (deep enough to hide DRAM-class latency -- the act stream evicts
// this scratch from L2). Loss capture is hoisted to a per-chunk uniform
// branch so the hot 8-diagonal body carries no per-diagonal checks.
// Folds the final mean via ticket atomic (last CTA, fixed-order sum).
// ---------------------------------------------------------------------------
__global__ void __launch_bounds__(32, 1) alpha_kernel(const int* __restrict__ tlen,
                                                      const int* __restrict__ ulen,
                                                      float* __restrict__ out) {
    __shared__ __align__(16) float s_bl[SLOTS][PITCH];
    __shared__ __align__(16) float s_em[SLOTS][PITCH];
    __shared__ __align__(16) float s_b0[DIAGS];

    int n = blockIdx.x;
    int L = threadIdx.x;
    const float* bld = g_bld + (size_t)n * DIAG_SZ;
    const float* emd = g_emd + (size_t)n * DIAG_SZ;
    const float* b0g = g_b0  + n * DIAGS;

    int Tn = __ldg(tlen + n);
    int Un = __ldg(ulen + n);
    int dLoss = Tn - 1 + Un;

    unsigned int sbl = (unsigned int)__cvta_generic_to_shared(&s_bl[0][0]);
    unsigned int sem = (unsigned int)__cvta_generic_to_shared(&s_em[0][0]);
    unsigned int sb0 = (unsigned int)__cvta_generic_to_shared(&s_b0[0]);

    // Copy global row -> ring slot (row & 63): one 16B segment per lane.
    auto issue_row = [&](int row) {
        unsigned int so = (unsigned int)(row & (SLOTS - 1)) * (PITCH * 4);
        cp16(sbl + so + 16u * L, bld + (size_t)row * PITCH + 4 * L);
        cp16(sem + so + 16u * L, emd + (size_t)row * PITCH + 4 * L);
    };

    // Prologue: b0 table (384 floats = 3 warp-instrs, own group), then
    // chunks 0..AHEAD-1, one commit group per chunk.
    cp16(sb0 + 16u * L,        b0g + 4 * L);
    cp16(sb0 + 16u * (L + 32), b0g + 4 * (L + 32));
    cp16(sb0 + 16u * (L + 64), b0g + 4 * (L + 64));
    cp_commit();
#pragma unroll
    for (int c = 0; c < AHEAD; ++c) {
#pragma unroll
        for (int k = 0; k < CH; ++k) issue_row(CH * c + k);
        cp_commit();
    }

    float a0 = 1.0f;                          // alpha[0][0] = exp(0)
    float a[4] = {0.0f, 0.0f, 0.0f, 0.0f};    // 0 == prob of invalid cell
    int   E = 0;                              // accumulated power-of-two scale

    if (dLoss == 0 && L == 0)                 // degenerate Tn=1, Un=0
        g_loss[n] = -__logf(__ldg(b0g));

    for (int c = 0; c < NCHUNK; ++c) {
        int rf = CH * (c + AHEAD);            // first row of chunk c+AHEAD
        if (rf < DIAGS) {
#pragma unroll
            for (int k = 0; k < CH; ++k) issue_row(rf + k);
        }
        cp_commit();                          // commit (possibly empty) group
        cp_wait7();                           // chunk c resident (8 in flight)
        __syncwarp();

        int d0 = CH * c + 1;                  // first diagonal of this chunk
        if ((unsigned)(dLoss - d0) < CH) {
            // ---- SLOW PATH: this chunk contains the loss diagonal ----
#pragma unroll
            for (int k = 0; k < CH; ++k) {
                int d = d0 + k;
                int s = (d - 1) & (SLOTS - 1);
                float4 blv = *reinterpret_cast<const float4*>(&s_bl[s][4 * L]);
                float4 emv = *reinterpret_cast<const float4*>(&s_em[s][4 * L]);
                float  b00 = s_b0[d - 1];

                float nb = __shfl_up_sync(0xffffffffu, a[3], 1);
                nb = (L == 0) ? a0 : nb;

                float t0 = fmaf(nb,   emv.x, a[0] * blv.x);
                float t1 = fmaf(a[0], emv.y, a[1] * blv.y);
                float t2 = fmaf(a[1], emv.z, a[2] * blv.z);
                float t3 = fmaf(a[2], emv.w, a[3] * blv.w);
                a0 *= b00;
                a[0] = t0; a[1] = t1; a[2] = t2; a[3] = t3;

                if (d == dLoss) {              // warp-uniform
                    float fin = (Un == 0) ? __ldg(b0g + dLoss)
                              : __ldg(bld + (size_t)dLoss * PITCH + Un - 1);
                    float lv;
                    if (Un == 0) {
                        lv = a0;
                    } else {
                        int tl = (Un - 1) >> 2, jj = (Un - 1) & 3;
                        float v = (jj == 0) ? t0 : (jj == 1) ? t1
                                : (jj == 2) ? t2 : t3;
                        lv = __shfl_sync(0xffffffffu, v, tl);
                    }
                    if (L == 0)
                        g_loss[n] = -(__logf(lv)
                                      + (float)E * 0.69314718055994531f
                                      + __logf(fin));
                }
            }
        } else {
            // ---- FAST PATH: no checks, pure recursion ----
#pragma unroll
            for (int k = 0; k < CH; ++k) {
                int d = d0 + k;
                int s = (d - 1) & (SLOTS - 1);
                float4 blv = *reinterpret_cast<const float4*>(&s_bl[s][4 * L]);
                float4 emv = *reinterpret_cast<const float4*>(&s_em[s][4 * L]);
                float  b00 = s_b0[d - 1];

                float nb = __shfl_up_sync(0xffffffffu, a[3], 1);
                nb = (L == 0) ? a0 : nb;

                float t0 = fmaf(nb,   emv.x, a[0] * blv.x);
                float t1 = fmaf(a[0], emv.y, a[1] * blv.y);
                float t2 = fmaf(a[1], emv.z, a[2] * blv.z);
                float t3 = fmaf(a[2], emv.w, a[3] * blv.w);
                a0 *= b00;
                a[0] = t0; a[1] = t1; a[2] = t2; a[3] = t3;
            }
        }

        // Renormalize by exact power of two (every 8 diagonals).
        float m = fmaxf(fmaxf(a[0], a[1]), fmaxf(a[2], a[3]));
        m = fmaxf(m, a0);
        unsigned mb = __reduce_max_sync(0xffffffffu, __float_as_uint(m));
        int e = (int)(mb >> 23) - 127;                        // biased exponent
        float sc = __int_as_float((unsigned)(127 - e) << 23); // 2^-e, exact
        a[0] *= sc; a[1] *= sc; a[2] *= sc; a[3] *= sc; a0 *= sc;
        E += e;
    }

    // Fold the mean: last CTA to arrive sums all losses in fixed order.
    __syncwarp();
    __threadfence();
    if (L == 0) {
        unsigned t = atomicAdd(&g_ticket, 1u);
        if (t == N_DIM - 1) {
            __threadfence();
            float s = 0.0f;
#pragma unroll
            for (int i = 0; i < N_DIM; ++i) s += g_loss[i];
            out[0] = s / (float)N_DIM;
            g_ticket = 0;                      // reset for next graph replay
        }
    }
}

extern "C" void kernel_launch(void* const* d_in, const int* in_sizes, int n_in,
                              void* d_out, int out_size) {
    const float* act  = (const float*)d_in[0];
    const int*   tgt  = (const int*)  d_in[1];
    const int*   tlen = (const int*)  d_in[2];
    const int*   ulen = (const int*)  d_in[3];
    float*       out  = (float*)      d_out;

    int blocks = (ROWS + 7) / 8;              // one warp per row, 8 warps/block
    lse_kernel<<<blocks, 256>>>(act, tgt);
    alpha_kernel<<<N_DIM, 32>>>(tlen, ulen, out);
}